// round 16
// baseline (speedup 1.0000x reference)
#include <cuda_runtime.h>
#include <cuda_bf16.h>

#define KOBJ 512
#define MAXN 131072
#define EPSF 1e-9f
#define HPB  136      // even; 80000/136 -> 589 blocks
#define NSLOT 16      // atomic slot spreading (hit pass only)

// ---------------- device scratch (no allocations allowed) ----------------
__device__ unsigned long long g_key[KOBJ * NSLOT];
__device__ float g_cnt[KOBJ * NSLOT], g_num[KOBJ * NSLOT], g_den[KOBJ * NSLOT];
__device__ float g_att[KOBJ], g_rep[KOBJ];
__device__ float g_cntc[KOBJ], g_numc[KOBJ], g_denc[KOBJ];
__device__ float g_xa[KOBJ], g_ya[KOBJ], g_qa[KOBJ], g_ba[KOBJ];
__device__ float g_noise_sum, g_noise_cnt, g_cc2;
__device__ unsigned g_ctrA, g_ctrB;
__device__ __align__(16) float g_hx[MAXN];   // SoA hit staging
__device__ __align__(16) float g_hy[MAXN];
__device__ __align__(16) float g_hq[MAXN];
__device__ int   g_ht[MAXN];

// ---------------- helpers ----------------
__device__ __forceinline__ float fsqrt_approx(float x) {
    float y; asm("sqrt.approx.f32 %0, %1;" : "=f"(y) : "f"(x)); return y;
}
__device__ __forceinline__ unsigned long long pack2(float a, float b) {
    unsigned long long r; asm("mov.b64 %0, {%1,%2};" : "=l"(r) : "f"(a), "f"(b)); return r;
}
__device__ __forceinline__ void unpack2(unsigned long long v, float& a, float& b) {
    asm("mov.b64 {%0,%1}, %2;" : "=f"(a), "=f"(b) : "l"(v));
}
__device__ __forceinline__ unsigned long long add2(unsigned long long a, unsigned long long b) {
    unsigned long long r; asm("add.rn.f32x2 %0, %1, %2;" : "=l"(r) : "l"(a), "l"(b)); return r;
}
__device__ __forceinline__ unsigned long long fma2(unsigned long long a, unsigned long long b,
                                                   unsigned long long c) {
    unsigned long long r; asm("fma.rn.f32x2 %0, %1, %2, %3;" : "=l"(r) : "l"(a), "l"(b), "l"(c)); return r;
}
__device__ __forceinline__ float softclip(float x, float a) {
    float s = x / a;
    s = (s > 1.0f) ? __logf(s + 1.0f) : s;
    return s * a;
}
__device__ __forceinline__ float huber(float x, float d) {
    float ax = fabsf(x);
    return (ax < d) ? x * x : (d * d + 2.0f * d * (ax - d));
}

// ===== kernel A: per-hit pass (slot-spread atomics) + last-block gather =====
__global__ __launch_bounds__(256) void k_hits(
        const float* __restrict__ pb,  const float* __restrict__ cc,
        const float* __restrict__ pe,  const float* __restrict__ pp,
        const float* __restrict__ pt,  const float* __restrict__ pid,
        const int*   __restrict__ tix, const float* __restrict__ te,
        const float* __restrict__ tp,  const float* __restrict__ tt,
        int n)
{
    int i = blockIdx.x * blockDim.x + threadIdx.x;
    int slot = blockIdx.x & (NSLOT - 1);
    float cc2 = 0.f, nsum = 0.f, ncnt = 0.f;
    if (i < n) {
        float b  = fminf(fmaxf(pb[i], 1e-6f), 1.0f - 1e-6f);
        float at = 0.5f * __logf(__fdividef(1.0f + b, 1.0f - b));   // atanh(b)
        float q  = at * at + 0.1f;                                   // + Q_MIN
        float x = cc[2 * i], y = cc[2 * i + 1];
        cc2 = x * x + y * y;
        int t = tix[i];
        g_hx[i] = x; g_hy[i] = y; g_hq[i] = q; g_ht[i] = t;

        if (t < 0) {
            nsum = b; ncnt = 1.0f;
        } else {
            int ts = t * NSLOT + slot;
            atomicAdd(&g_cnt[ts], 1.0f);
            // argmax beta, ties -> lowest index (matches jnp.argmax)
            unsigned long long key =
                ((unsigned long long)__float_as_uint(b) << 32) |
                (unsigned long long)(0xFFFFFFFFu - (unsigned)i);
            atomicMax(&g_key[ts], key);

            // payload losses
            float tei = te[i];
            float ed  = fabsf(tei - pe[i]);
            float el  = softclip(10.0f * __expf(-0.1f * ed * ed) + 0.01f * ed, 10.0f);

            float dpx = tp[2 * i]     - pp[2 * i];
            float dpy = tp[2 * i + 1] - pp[2 * i + 1];
            float d2p = dpx * dpx + dpy * dpy;
            float pl  = softclip(huber(fsqrt_approx(d2p * 0.01f + 0.01f), 10.0f), 3.0f);

            float tl  = softclip(huber(tt[i] - pt[i], 2.0f), 6.0f);

            float cl = 0.f;
            #pragma unroll
            for (int j = 0; j < 6; j++) { float v = pid[6 * i + j]; cl += v * v; }
            cl *= (1e-8f / 6.0f);

            float payload = el + pl + tl + cl;
            float ew = (tei > 10.0f) ? 1.0f : (tei - 0.5f) * (1.0f / 9.5f);
            ew = fmaxf(ew, 0.0f);
            float pw = b * ew;
            atomicAdd(&g_num[ts], payload * pw);
            atomicAdd(&g_den[ts], pw);
        }
    }
    // warp-aggregate scalar sums -> 1 atomic per warp each
    #pragma unroll
    for (int o = 16; o; o >>= 1) {
        cc2  += __shfl_down_sync(0xFFFFFFFFu, cc2,  o);
        nsum += __shfl_down_sync(0xFFFFFFFFu, nsum, o);
        ncnt += __shfl_down_sync(0xFFFFFFFFu, ncnt, o);
    }
    if ((threadIdx.x & 31) == 0) {
        atomicAdd(&g_cc2, cc2);
        if (nsum != 0.f) atomicAdd(&g_noise_sum, nsum);
        if (ncnt != 0.f) atomicAdd(&g_noise_cnt, ncnt);
    }

    // ---- last-block: slot reduce + alpha gather ----
    __threadfence();
    __syncthreads();
    __shared__ unsigned s_last;
    if (threadIdx.x == 0) s_last = (atomicAdd(&g_ctrA, 1u) == gridDim.x - 1u);
    __syncthreads();
    if (!s_last) return;
    if (threadIdx.x == 0) g_ctrA = 0u;

    for (int k = threadIdx.x; k < KOBJ; k += blockDim.x) {
        float c = 0.f, nm = 0.f, dn = 0.f;
        unsigned long long key = 0ull;
        #pragma unroll
        for (int sl = 0; sl < NSLOT; sl++) {
            int ts = k * NSLOT + sl;
            c  += g_cnt[ts];
            nm += g_num[ts];
            dn += g_den[ts];
            unsigned long long kk = g_key[ts];
            key = (kk > key) ? kk : key;
        }
        g_cntc[k] = c; g_numc[k] = nm; g_denc[k] = dn;

        if (c > 0.f) {
            unsigned enc = (unsigned)(key & 0xFFFFFFFFull);
            int a = (int)(0xFFFFFFFFu - enc);
            float b  = fminf(fmaxf(pb[a], 1e-6f), 1.0f - 1e-6f);
            float at = 0.5f * __logf(__fdividef(1.0f + b, 1.0f - b));
            g_qa[k] = at * at + 0.1f;
            g_xa[k] = cc[2 * a];
            g_ya[k] = cc[2 * a + 1];
            g_ba[k] = b;
        } else {
            g_qa[k] = 0.f; g_xa[k] = 1e18f; g_ya[k] = 0.f; g_ba[k] = 0.f;
        }
    }
}

// ======== kernel B: packed-f32x2 pair pass + (last block) final reduce ======
__global__ __launch_bounds__(512, 4) void k_pairs(float* __restrict__ out,
                                                  int n, int out_size) {
    int k = threadIdx.x;

    // distributed zeroing of the hit-pass slot arrays for the next replay
    if (blockIdx.x < 32) {
        int base = blockIdx.x * 512 + k;                 // 16384 threads
        for (int j = base; j < KOBJ * NSLOT; j += 32 * 512) {
            g_key[j] = 0ull;
            g_cnt[j] = 0.f; g_num[j] = 0.f; g_den[j] = 0.f;
        }
    }

    float ax = g_xa[k], ay = g_ya[k], qa = g_qa[k];
    int s = blockIdx.x * HPB;
    int m = min(n - s, HPB);
    int mp = m >> 1;                        // full packed pairs
    int mc = (m + 1) >> 1;                  // pairs to stage (ceil)

    __shared__ unsigned long long shx[HPB / 2], shy[HPB / 2], shq[HPB / 2];
    if (k < mc) {
        int g = (s >> 1) + k;
        shx[k] = ((const unsigned long long*)g_hx)[g];
        shy[k] = ((const unsigned long long*)g_hy)[g];
        shq[k] = ((const unsigned long long*)g_hq)[g];
    }
    __syncthreads();

    const unsigned long long nax2 = pack2(-ax, -ax);
    const unsigned long long nay2 = pack2(-ay, -ay);
    const unsigned long long eps2 = pack2(1e-6f, 1e-6f);
    const unsigned long long cm1  = pack2(-1.0f, -1.0f);
    const unsigned long long c1   = pack2(1.0f, 1.0f);

    float ar0 = 0.f, ar1 = 0.f;
    if (mp == HPB / 2) {
        #pragma unroll 4
        for (int j = 0; j < HPB / 2; j++) {
            unsigned long long dx2 = add2(shx[j], nax2);
            unsigned long long dy2 = add2(shy[j], nay2);
            unsigned long long d2  = fma2(dx2, dx2, eps2);
            d2 = fma2(dy2, dy2, d2);
            float da, db; unpack2(d2, da, db);
            float sa = fsqrt_approx(da), sb = fsqrt_approx(db);
            unsigned long long w2 = fma2(pack2(sa, sb), cm1, c1);   // 1 - s
            float wa, wb; unpack2(w2, wa, wb);
            float qlo, qhi; unpack2(shq[j], qlo, qhi);
            ar0 = fmaf(fmaxf(wa, 0.f), qlo, ar0);
            ar1 = fmaf(fmaxf(wb, 0.f), qhi, ar1);
        }
    } else {
        for (int j = 0; j < mp; j++) {
            unsigned long long dx2 = add2(shx[j], nax2);
            unsigned long long dy2 = add2(shy[j], nay2);
            unsigned long long d2  = fma2(dx2, dx2, eps2);
            d2 = fma2(dy2, dy2, d2);
            float da, db; unpack2(d2, da, db);
            float sa = fsqrt_approx(da), sb = fsqrt_approx(db);
            unsigned long long w2 = fma2(pack2(sa, sb), cm1, c1);
            float wa, wb; unpack2(w2, wa, wb);
            float qlo, qhi; unpack2(shq[j], qlo, qhi);
            ar0 = fmaf(fmaxf(wa, 0.f), qlo, ar0);
            ar1 = fmaf(fmaxf(wb, 0.f), qhi, ar1);
        }
        if (m & 1) {                        // scalar tail element m-1
            int j = m - 1;
            float hx = ((const float*)shx)[j];
            float hy = ((const float*)shy)[j];
            float hq = ((const float*)shq)[j];
            float dx = hx - ax, dy = hy - ay;
            float d2 = fmaf(dx, dx, 1e-6f); d2 = fmaf(dy, dy, d2);
            float w = 1.0f - fsqrt_approx(d2);
            ar0 = fmaf(fmaxf(w, 0.f), hq, ar0);
        }
    }
    atomicAdd(&g_rep[k], (ar0 + ar1) * qa);

    // O(N) side path: attraction + subtract member's repulsion hinge
    if (k < m) {
        float hx = ((const float*)shx)[k];
        float hy = ((const float*)shy)[k];
        float hq = ((const float*)shq)[k];
        int t = g_ht[s + k];
        if (t >= 0) {
            float axt = g_xa[t], ayt = g_ya[t], qat = g_qa[t];
            float dx = hx - axt, dy = hy - ayt;
            float d2  = dx * dx + dy * dy;
            float d2e = fmaf(dx, dx, 1e-6f); d2e = fmaf(dy, dy, d2e);
            float wm  = fmaxf(1.0f - fsqrt_approx(d2e), 0.f);
            atomicAdd(&g_att[t],  d2 * hq * qat);
            atomicAdd(&g_rep[t], -wm * hq * qat);
        }
    }

    // ---- last-block final reduce + zero small scratch for next replay ----
    __threadfence();
    __syncthreads();
    __shared__ unsigned s_last;
    if (k == 0) s_last = (atomicAdd(&g_ctrB, 1u) == gridDim.x - 1u);
    __syncthreads();
    if (!s_last) return;

    float c  = g_cntc[k];
    bool  hh = c > 0.f;
    float la = hh ? g_att[k] / (c + EPSF) : 0.f;
    float lr = hh ? g_rep[k] / ((float)n - c + EPSF) : 0.f;
    float lp = hh ? g_numc[k] / (g_denc[k] + EPSF) : 0.f;
    float lb = hh ? (1.0f - g_ba[k]) : 0.f;
    float no = hh ? 1.0f : 0.f;
    float nse = g_noise_sum, nsc = g_noise_cnt, ccs = g_cc2;

    g_att[k] = 0.f; g_rep[k] = 0.f;
    if (k == 0) { g_noise_sum = 0.f; g_noise_cnt = 0.f; g_cc2 = 0.f; g_ctrB = 0u; }

    __shared__ float red[5][16];
    float v[5] = {la, lr, lp, lb, no};
    int lane = k & 31, w = k >> 5;
    #pragma unroll
    for (int j = 0; j < 5; j++) {
        float t = v[j];
        #pragma unroll
        for (int o = 16; o; o >>= 1) t += __shfl_down_sync(0xFFFFFFFFu, t, o);
        if (lane == 0) red[j][w] = t;
    }
    __syncthreads();
    if (k == 0) {
        float acc[5] = {0.f, 0.f, 0.f, 0.f, 0.f};
        #pragma unroll
        for (int w2 = 0; w2 < 16; w2++)
            #pragma unroll
            for (int j = 0; j < 5; j++) acc[j] += red[j][w2];
        float nobj = acc[4] + EPSF;
        float total = (acc[0] + acc[1] + acc[2] + acc[3]) / nobj
                    + nse / (nsc + EPSF)
                    + 0.001f * ccs / ((float)n * 2.0f);
        for (int i = 0; i < out_size; i++) out[i] = total;
    }
}

// ---------------- launch ----------------
extern "C" void kernel_launch(void* const* d_in, const int* in_sizes, int n_in,
                              void* d_out, int out_size) {
    const float* pb  = (const float*)d_in[0];   // pred_beta    (N,1)
    const float* cc  = (const float*)d_in[1];   // pred_ccoords (N,2)
    const float* pe  = (const float*)d_in[2];   // pred_energy  (N,1)
    const float* pp  = (const float*)d_in[3];   // pred_pos     (N,2)
    const float* pt  = (const float*)d_in[4];   // pred_time    (N,1)
    const float* pid = (const float*)d_in[5];   // pred_id      (N,6)
    const int*   tix = (const int*)  d_in[6];   // t_idx        (N,1)
    const float* te  = (const float*)d_in[7];   // t_energy     (N,1)
    const float* tp  = (const float*)d_in[8];   // t_pos        (N,2)
    const float* tt  = (const float*)d_in[9];   // t_time       (N,1)
    // d_in[10] = t_pid, unused by the reference loss

    int n = in_sizes[0];

    k_hits<<<(n + 255) / 256, 256>>>(pb, cc, pe, pp, pt, pid, tix, te, tp, tt, n);
    k_pairs<<<(n + HPB - 1) / HPB, KOBJ>>>((float*)d_out, n, out_size);
}